// round 15
// baseline (speedup 1.0000x reference)
#include <cuda_runtime.h>
#include <cstdint>

#define NSOL   8
#define NBATCH 4
#define ACC_TOTAL (NBATCH * NSOL)   // 32

#define TOTAL_BLOCKS 740            // 5 CTAs/SM x 148 SMs -> single resident wave
#define L_BLOCKS     256            // these do the load/vol part first, then steal
#define TILE         4096           // nnz per stolen tile (128 pairs x 32 steps)

// zero-initialized at module load; finalize re-zeros them after each use.
// [0..31] a_energy (b*8+s), [32..63] load (b*8+s), [64..67] vol[b]
__device__ float g_acc[ACC_TOTAL * 2 + NBATCH];
__device__ int   g_ticket;
__device__ int   g_work;            // tile-stealing counter

// ---------------------------------------------------------------------------
// Last-finishing block computes the loss, then resets all state for the next
// graph replay.
__device__ __forceinline__ void try_finalize(float* out) {
    __syncthreads();
    if (threadIdx.x != 0) return;
    __threadfence();
    int old = atomicAdd(&g_ticket, 1);
    if (old != TOTAL_BLOCKS - 1) return;
    __threadfence();
    float kkt_sum = 0.0f, comp_sum = 0.0f;
#pragma unroll
    for (int b = 0; b < NBATCH; b++) {
        float vol = g_acc[2 * ACC_TOTAL + b];
#pragma unroll
        for (int s = 0; s < NSOL; s++) {
            float ae = g_acc[b * NSOL + s];
            float ld = g_acc[ACC_TOTAL + b * NSOL + s];
            float sigma = ld / fmaxf(ae, 1e-4f);
            kkt_sum  += (0.5f * ae * sigma - ld) * sigma / vol;
            comp_sum += sigma * ld / vol;
        }
    }
    float kkt  = kkt_sum  / (float)(NBATCH * NSOL);
    float comp = -comp_sum / (float)(NBATCH * NSOL);
    out[0] = 0.5f * comp + 0.5f * kkt;   // LAMB_COMP = 0.5
#pragma unroll
    for (int i = 0; i < ACC_TOTAL * 2 + NBATCH; i++) g_acc[i] = 0.0f;
    g_work = 0;
    __threadfence();
    g_ticket = 0;
}

// ---------------------------------------------------------------------------
__device__ __forceinline__ void energy_step(
    int r, int c, float v, int h, int N1, int N2, int N3,
    const float4* __restrict__ x4, float acc[NBATCH][4])
{
    // .cg: bypass L1 line fill (hit rate ~2%), fetch only the needed sectors
    float4 xr = __ldcg(&x4[(size_t)r * 2 + h]);
    float4 xc = __ldcg(&x4[(size_t)c * 2 + h]);
    float t0 = xr.x * xc.x, t1 = xr.y * xc.y;
    float t2 = xr.z * xc.z, t3 = xr.w * xc.w;
    int b = (r >= N2) ? ((r >= N3) ? 3 : 2) : ((r >= N1) ? 1 : 0);
    float v0 = (b == 0) ? v : 0.0f;
    float v1 = (b == 1) ? v : 0.0f;
    float v2 = (b == 2) ? v : 0.0f;
    float v3 = (b == 3) ? v : 0.0f;
    acc[0][0] += v0 * t0; acc[0][1] += v0 * t1; acc[0][2] += v0 * t2; acc[0][3] += v0 * t3;
    acc[1][0] += v1 * t0; acc[1][1] += v1 * t1; acc[1][2] += v1 * t2; acc[1][3] += v1 * t3;
    acc[2][0] += v2 * t0; acc[2][1] += v2 * t1; acc[2][2] += v2 * t2; acc[2][3] += v2 * t3;
    acc[3][0] += v3 * t0; acc[3][1] += v3 * t1; acc[3][2] += v3 * t2; acc[3][3] += v3 * t3;
}

// ---------------------------------------------------------------------------
// Persistent fused kernel, single resident wave + dynamic tile stealing.
// Blocks [0, L_BLOCKS) run the load/vol reduction first, then all blocks
// steal 4096-nnz tiles for the COO bilinear form. Full tiles take an
// unguarded int-arithmetic fast path; the single remainder tile is guarded.
__global__ __launch_bounds__(256)
void fused_kernel(const void*  __restrict__ Aind_raw,
                  const float* __restrict__ Aval,
                  const float* __restrict__ x,
                  const float* __restrict__ rhs,
                  const float* __restrict__ mass,
                  int nnz, int N, float* __restrict__ out)
{
    // ============== LOAD / VOL PART (blocks 0..255, done first) ==============
    if (blockIdx.x < L_BLOCKS) {
        int lb     = blockIdx.x;
        int b      = lb & (NBATCH - 1);
        int xblock = lb >> 2;                // [0, 64)
        const float4* __restrict__ x4 = reinterpret_cast<const float4*>(x);
        const float4* __restrict__ r4 = reinterpret_cast<const float4*>(rhs);

        float lacc[NSOL];
#pragma unroll
        for (int s = 0; s < NSOL; s++) lacc[s] = 0.0f;
        float volacc = 0.0f;

        int stride = (L_BLOCKS / NBATCH) * 256;
        for (int n = xblock * 256 + threadIdx.x; n < N; n += stride) {
            size_t i = (size_t)b * N + n;
            float  m = mass[i];
            float4 x0 = x4[i * 2 + 0], x1 = x4[i * 2 + 1];
            float4 r0 = r4[i * 2 + 0], r1 = r4[i * 2 + 1];
            lacc[0] += m * r0.x * x0.x;  lacc[1] += m * r0.y * x0.y;
            lacc[2] += m * r0.z * x0.z;  lacc[3] += m * r0.w * x0.w;
            lacc[4] += m * r1.x * x1.x;  lacc[5] += m * r1.y * x1.y;
            lacc[6] += m * r1.z * x1.z;  lacc[7] += m * r1.w * x1.w;
            volacc += m;
        }

        __shared__ float swarp2[8 * (NSOL + 1)];
        int lane = threadIdx.x & 31;
        int wid  = threadIdx.x >> 5;
#pragma unroll
        for (int j = 0; j < NSOL + 1; j++) {
            float val = (j < NSOL) ? lacc[j] : volacc;
#pragma unroll
            for (int o = 16; o > 0; o >>= 1)
                val += __shfl_down_sync(0xFFFFFFFFu, val, o);
            if (lane == 0) swarp2[wid * (NSOL + 1) + j] = val;
        }
        __syncthreads();
        if (threadIdx.x < NSOL + 1) {
            float total = 0.0f;
#pragma unroll
            for (int w = 0; w < 8; w++) total += swarp2[w * (NSOL + 1) + threadIdx.x];
            if (threadIdx.x < NSOL)
                atomicAdd(&g_acc[ACC_TOTAL + b * NSOL + threadIdx.x], total);
            else
                atomicAdd(&g_acc[2 * ACC_TOTAL + b], total);
        }
        __syncthreads();
    }

    // ============== ENERGY PART (all blocks, tile stealing) ==============
    // per-block dtype peek: int64 values < 2^31 have zero high words
    unsigned any = 0;
    {
        const unsigned* w = (const unsigned*)Aind_raw;
#pragma unroll
        for (int j = 0; j < 16; j++) any |= w[2 * j + 1];
    }
    const int idx64 = (any == 0);

    float acc[NBATCH][4];
#pragma unroll
    for (int b = 0; b < NBATCH; b++)
#pragma unroll
        for (int s = 0; s < 4; s++) acc[b][s] = 0.0f;

    const int N1 = N, N2 = 2 * N, N3 = 3 * N;
    const float4* __restrict__ x4 = reinterpret_cast<const float4*>(x);

    int pair = threadIdx.x >> 1;   // 0..127
    int h    = threadIdx.x & 1;    // float4 half (sols 0-3 / 4-7)

    const int ntiles_full = nnz / TILE;     // tiles needing no bounds checks

    __shared__ int s_tile;
    for (;;) {
        if (threadIdx.x == 0) s_tile = atomicAdd(&g_work, 1);
        __syncthreads();
        int tile = s_tile;
        __syncthreads();           // protect s_tile before next overwrite
        if (tile > ntiles_full) break;

        if (tile < ntiles_full) {
            // ---- FAST PATH: full tile, int arithmetic, no guards ----
            int p = tile * TILE + pair;
            if (idx64) {
                const long long* __restrict__ Aind = (const long long*)Aind_raw;
#pragma unroll
                for (int i = 0; i < TILE / 128; i += 4) {
                    int pa = p + (i + 0) * 128;
                    int pb = p + (i + 1) * 128;
                    int pc = p + (i + 2) * 128;
                    int pd = p + (i + 3) * 128;
                    int   ra = (int)__ldcs(&Aind[pa]);
                    int   ca = (int)__ldcs(&Aind[(size_t)nnz + pa]);
                    float va = __ldcs(&Aval[pa]);
                    int   rb = (int)__ldcs(&Aind[pb]);
                    int   cb = (int)__ldcs(&Aind[(size_t)nnz + pb]);
                    float vb = __ldcs(&Aval[pb]);
                    int   rc = (int)__ldcs(&Aind[pc]);
                    int   cc = (int)__ldcs(&Aind[(size_t)nnz + pc]);
                    float vc = __ldcs(&Aval[pc]);
                    int   rd = (int)__ldcs(&Aind[pd]);
                    int   cd = (int)__ldcs(&Aind[(size_t)nnz + pd]);
                    float vd = __ldcs(&Aval[pd]);
                    energy_step(ra, ca, va, h, N1, N2, N3, x4, acc);
                    energy_step(rb, cb, vb, h, N1, N2, N3, x4, acc);
                    energy_step(rc, cc, vc, h, N1, N2, N3, x4, acc);
                    energy_step(rd, cd, vd, h, N1, N2, N3, x4, acc);
                }
            } else {
                const int* __restrict__ Aind = (const int*)Aind_raw;
#pragma unroll
                for (int i = 0; i < TILE / 128; i += 4) {
                    int pa = p + (i + 0) * 128;
                    int pb = p + (i + 1) * 128;
                    int pc = p + (i + 2) * 128;
                    int pd = p + (i + 3) * 128;
                    int   ra = __ldcs(&Aind[pa]);
                    int   ca = __ldcs(&Aind[(size_t)nnz + pa]);
                    float va = __ldcs(&Aval[pa]);
                    int   rb = __ldcs(&Aind[pb]);
                    int   cb = __ldcs(&Aind[(size_t)nnz + pb]);
                    float vb = __ldcs(&Aval[pb]);
                    int   rc = __ldcs(&Aind[pc]);
                    int   cc = __ldcs(&Aind[(size_t)nnz + pc]);
                    float vc = __ldcs(&Aval[pc]);
                    int   rd = __ldcs(&Aind[pd]);
                    int   cd = __ldcs(&Aind[(size_t)nnz + pd]);
                    float vd = __ldcs(&Aval[pd]);
                    energy_step(ra, ca, va, h, N1, N2, N3, x4, acc);
                    energy_step(rb, cb, vb, h, N1, N2, N3, x4, acc);
                    energy_step(rc, cc, vc, h, N1, N2, N3, x4, acc);
                    energy_step(rd, cd, vd, h, N1, N2, N3, x4, acc);
                }
            }
        } else {
            // ---- TAIL: remainder tile (at most one block takes this) ----
            if (idx64) {
                const long long* __restrict__ Aind = (const long long*)Aind_raw;
                for (int p = ntiles_full * TILE + pair; p < nnz; p += 128) {
                    int   r = (int)__ldcs(&Aind[p]);
                    int   c = (int)__ldcs(&Aind[(size_t)nnz + p]);
                    float v = __ldcs(&Aval[p]);
                    energy_step(r, c, v, h, N1, N2, N3, x4, acc);
                }
            } else {
                const int* __restrict__ Aind = (const int*)Aind_raw;
                for (int p = ntiles_full * TILE + pair; p < nnz; p += 128) {
                    int   r = __ldcs(&Aind[p]);
                    int   c = __ldcs(&Aind[(size_t)nnz + p]);
                    float v = __ldcs(&Aval[p]);
                    energy_step(r, c, v, h, N1, N2, N3, x4, acc);
                }
            }
            // after the tail there is no more work
            break;
        }
    }

    // parity-preserving reduction -> lanes 0/1 -> shared -> 32 atomics
    {
        __shared__ float swarp[8 * ACC_TOTAL];
        int lane = threadIdx.x & 31;
        int wid  = threadIdx.x >> 5;
#pragma unroll
        for (int b = 0; b < NBATCH; b++)
#pragma unroll
            for (int s = 0; s < 4; s++) {
                float val = acc[b][s];
                val += __shfl_down_sync(0xFFFFFFFFu, val, 16);
                val += __shfl_down_sync(0xFFFFFFFFu, val, 8);
                val += __shfl_down_sync(0xFFFFFFFFu, val, 4);
                val += __shfl_down_sync(0xFFFFFFFFu, val, 2);
                if (lane < 2)   // lane0: s 0-3, lane1: s 4-7
                    swarp[wid * ACC_TOTAL + b * NSOL + h * 4 + s] = val;
            }
        __syncthreads();
        if (threadIdx.x < ACC_TOTAL) {
            float total = 0.0f;
#pragma unroll
            for (int w = 0; w < 8; w++) total += swarp[w * ACC_TOTAL + threadIdx.x];
            atomicAdd(&g_acc[threadIdx.x], total);
        }
    }

    try_finalize(out);
}

// ---------------------------------------------------------------------------
extern "C" void kernel_launch(void* const* d_in, const int* in_sizes, int n_in,
                              void* d_out, int out_size)
{
    // identify inputs by element count:
    // A_ind = 2*NNZ (max), A_val = NNZ, mass = B*N (min),
    // subspace = 4*B*N, x_hat = rhs = 8*B*N.
    long long maxs = -1, mins = 0x7fffffffffffffffLL;
    for (int i = 0; i < n_in; i++) {
        long long s = in_sizes[i];
        if (s > maxs) maxs = s;
        if (s < mins) mins = s;
    }
    int i_aind = -1, i_aval = -1, i_mass = -1, i_xr0 = -1, i_xr1 = -1;
    for (int i = 0; i < n_in; i++) {
        long long s = in_sizes[i];
        if (s == maxs)            i_aind = i;
        else if (2 * s == maxs)   i_aval = i;
        else if (s == mins)       i_mass = i;
        else if (s == 8 * mins) { if (i_xr0 < 0) i_xr0 = i; else i_xr1 = i; }
    }
    // dict order -> pair at (0,1) with x_hat first; alphabetical -> rhs first
    int i_x   = (i_xr0 == 0) ? i_xr0 : i_xr1;
    int i_rhs = (i_xr0 == 0) ? i_xr1 : i_xr0;

    const float* x_hat = (const float*)d_in[i_x];
    const float* rhs   = (const float*)d_in[i_rhs];
    const void*  A_ind = d_in[i_aind];
    const float* A_val = (const float*)d_in[i_aval];
    const float* mass  = (const float*)d_in[i_mass];

    int nnz = in_sizes[i_aval];
    int N   = in_sizes[i_mass] / NBATCH;

    fused_kernel<<<TOTAL_BLOCKS, 256>>>(A_ind, A_val, x_hat, rhs, mass,
                                        nnz, N, (float*)d_out);
}

// round 16
// speedup vs baseline: 1.0550x; 1.0550x over previous
#include <cuda_runtime.h>
#include <cstdint>

#define NSOL   8
#define NBATCH 4
#define ACC_TOTAL (NBATCH * NSOL)   // 32

#define TOTAL_BLOCKS 740            // 5 CTAs/SM x 148 SMs -> single resident wave
#define L_BLOCKS     256            // these do the load/vol part first, then steal
#define TILE         2048           // nnz per stolen tile (128 pairs x 16 steps)

// zero-initialized at module load; finalize re-zeros them after each use.
// [0..31] a_energy (b*8+s), [32..63] load (b*8+s), [64..67] vol[b]
__device__ float g_acc[ACC_TOTAL * 2 + NBATCH];
__device__ int   g_ticket;
__device__ int   g_work;            // tile-stealing counter

// ---------------------------------------------------------------------------
// Last-finishing block computes the loss, then resets all state for the next
// graph replay.
__device__ __forceinline__ void try_finalize(float* out) {
    __syncthreads();
    if (threadIdx.x != 0) return;
    __threadfence();
    int old = atomicAdd(&g_ticket, 1);
    if (old != TOTAL_BLOCKS - 1) return;
    __threadfence();
    float kkt_sum = 0.0f, comp_sum = 0.0f;
#pragma unroll
    for (int b = 0; b < NBATCH; b++) {
        float vol = g_acc[2 * ACC_TOTAL + b];
#pragma unroll
        for (int s = 0; s < NSOL; s++) {
            float ae = g_acc[b * NSOL + s];
            float ld = g_acc[ACC_TOTAL + b * NSOL + s];
            float sigma = ld / fmaxf(ae, 1e-4f);
            kkt_sum  += (0.5f * ae * sigma - ld) * sigma / vol;
            comp_sum += sigma * ld / vol;
        }
    }
    float kkt  = kkt_sum  / (float)(NBATCH * NSOL);
    float comp = -comp_sum / (float)(NBATCH * NSOL);
    out[0] = 0.5f * comp + 0.5f * kkt;   // LAMB_COMP = 0.5
#pragma unroll
    for (int i = 0; i < ACC_TOTAL * 2 + NBATCH; i++) g_acc[i] = 0.0f;
    g_work = 0;
    __threadfence();
    g_ticket = 0;
}

// ---------------------------------------------------------------------------
__device__ __forceinline__ void energy_step(
    int r, int c, float v, int h, int N1, int N2, int N3,
    const float4* __restrict__ x4, float acc[NBATCH][4])
{
    // .cg: bypass L1 line fill (hit rate ~2%), fetch only the needed sectors
    float4 xr = __ldcg(&x4[(size_t)r * 2 + h]);
    float4 xc = __ldcg(&x4[(size_t)c * 2 + h]);
    float t0 = xr.x * xc.x, t1 = xr.y * xc.y;
    float t2 = xr.z * xc.z, t3 = xr.w * xc.w;
    int b = (r >= N2) ? ((r >= N3) ? 3 : 2) : ((r >= N1) ? 1 : 0);
    float v0 = (b == 0) ? v : 0.0f;
    float v1 = (b == 1) ? v : 0.0f;
    float v2 = (b == 2) ? v : 0.0f;
    float v3 = (b == 3) ? v : 0.0f;
    acc[0][0] += v0 * t0; acc[0][1] += v0 * t1; acc[0][2] += v0 * t2; acc[0][3] += v0 * t3;
    acc[1][0] += v1 * t0; acc[1][1] += v1 * t1; acc[1][2] += v1 * t2; acc[1][3] += v1 * t3;
    acc[2][0] += v2 * t0; acc[2][1] += v2 * t1; acc[2][2] += v2 * t2; acc[2][3] += v2 * t3;
    acc[3][0] += v3 * t0; acc[3][1] += v3 * t1; acc[3][2] += v3 * t2; acc[3][3] += v3 * t3;
}

// ---------------------------------------------------------------------------
// Persistent fused kernel, single resident wave + dynamic tile stealing.
// Blocks [0, L_BLOCKS) run the load/vol reduction first, then all blocks
// steal 2048-nnz tiles for the COO bilinear form. Full tiles take an
// unguarded int-arithmetic fast path; the single remainder tile is guarded.
__global__ __launch_bounds__(256)
void fused_kernel(const void*  __restrict__ Aind_raw,
                  const float* __restrict__ Aval,
                  const float* __restrict__ x,
                  const float* __restrict__ rhs,
                  const float* __restrict__ mass,
                  int nnz, int N, float* __restrict__ out)
{
    // ============== LOAD / VOL PART (blocks 0..255, done first) ==============
    if (blockIdx.x < L_BLOCKS) {
        int lb     = blockIdx.x;
        int b      = lb & (NBATCH - 1);
        int xblock = lb >> 2;                // [0, 64)
        const float4* __restrict__ x4 = reinterpret_cast<const float4*>(x);
        const float4* __restrict__ r4 = reinterpret_cast<const float4*>(rhs);

        float lacc[NSOL];
#pragma unroll
        for (int s = 0; s < NSOL; s++) lacc[s] = 0.0f;
        float volacc = 0.0f;

        int stride = (L_BLOCKS / NBATCH) * 256;
        for (int n = xblock * 256 + threadIdx.x; n < N; n += stride) {
            size_t i = (size_t)b * N + n;
            float  m = mass[i];
            float4 x0 = x4[i * 2 + 0], x1 = x4[i * 2 + 1];
            float4 r0 = r4[i * 2 + 0], r1 = r4[i * 2 + 1];
            lacc[0] += m * r0.x * x0.x;  lacc[1] += m * r0.y * x0.y;
            lacc[2] += m * r0.z * x0.z;  lacc[3] += m * r0.w * x0.w;
            lacc[4] += m * r1.x * x1.x;  lacc[5] += m * r1.y * x1.y;
            lacc[6] += m * r1.z * x1.z;  lacc[7] += m * r1.w * x1.w;
            volacc += m;
        }

        __shared__ float swarp2[8 * (NSOL + 1)];
        int lane = threadIdx.x & 31;
        int wid  = threadIdx.x >> 5;
#pragma unroll
        for (int j = 0; j < NSOL + 1; j++) {
            float val = (j < NSOL) ? lacc[j] : volacc;
#pragma unroll
            for (int o = 16; o > 0; o >>= 1)
                val += __shfl_down_sync(0xFFFFFFFFu, val, o);
            if (lane == 0) swarp2[wid * (NSOL + 1) + j] = val;
        }
        __syncthreads();
        if (threadIdx.x < NSOL + 1) {
            float total = 0.0f;
#pragma unroll
            for (int w = 0; w < 8; w++) total += swarp2[w * (NSOL + 1) + threadIdx.x];
            if (threadIdx.x < NSOL)
                atomicAdd(&g_acc[ACC_TOTAL + b * NSOL + threadIdx.x], total);
            else
                atomicAdd(&g_acc[2 * ACC_TOTAL + b], total);
        }
        __syncthreads();
    }

    // ============== ENERGY PART (all blocks, tile stealing) ==============
    // per-block dtype peek: int64 values < 2^31 have zero high words
    unsigned any = 0;
    {
        const unsigned* w = (const unsigned*)Aind_raw;
#pragma unroll
        for (int j = 0; j < 16; j++) any |= w[2 * j + 1];
    }
    const int idx64 = (any == 0);

    float acc[NBATCH][4];
#pragma unroll
    for (int b = 0; b < NBATCH; b++)
#pragma unroll
        for (int s = 0; s < 4; s++) acc[b][s] = 0.0f;

    const int N1 = N, N2 = 2 * N, N3 = 3 * N;
    const float4* __restrict__ x4 = reinterpret_cast<const float4*>(x);

    int pair = threadIdx.x >> 1;   // 0..127
    int h    = threadIdx.x & 1;    // float4 half (sols 0-3 / 4-7)

    const int ntiles_full = nnz / TILE;     // tiles needing no bounds checks

    __shared__ int s_tile;
    for (;;) {
        if (threadIdx.x == 0) s_tile = atomicAdd(&g_work, 1);
        __syncthreads();
        int tile = s_tile;
        __syncthreads();           // protect s_tile before next overwrite
        if (tile > ntiles_full) break;

        if (tile < ntiles_full) {
            // ---- FAST PATH: full tile, int arithmetic, no guards ----
            int p = tile * TILE + pair;
            if (idx64) {
                const long long* __restrict__ Aind = (const long long*)Aind_raw;
#pragma unroll
                for (int i = 0; i < TILE / 128; i += 4) {
                    int pa = p + (i + 0) * 128;
                    int pb = p + (i + 1) * 128;
                    int pc = p + (i + 2) * 128;
                    int pd = p + (i + 3) * 128;
                    int   ra = (int)__ldcs(&Aind[pa]);
                    int   ca = (int)__ldcs(&Aind[(size_t)nnz + pa]);
                    float va = __ldcs(&Aval[pa]);
                    int   rb = (int)__ldcs(&Aind[pb]);
                    int   cb = (int)__ldcs(&Aind[(size_t)nnz + pb]);
                    float vb = __ldcs(&Aval[pb]);
                    int   rc = (int)__ldcs(&Aind[pc]);
                    int   cc = (int)__ldcs(&Aind[(size_t)nnz + pc]);
                    float vc = __ldcs(&Aval[pc]);
                    int   rd = (int)__ldcs(&Aind[pd]);
                    int   cd = (int)__ldcs(&Aind[(size_t)nnz + pd]);
                    float vd = __ldcs(&Aval[pd]);
                    energy_step(ra, ca, va, h, N1, N2, N3, x4, acc);
                    energy_step(rb, cb, vb, h, N1, N2, N3, x4, acc);
                    energy_step(rc, cc, vc, h, N1, N2, N3, x4, acc);
                    energy_step(rd, cd, vd, h, N1, N2, N3, x4, acc);
                }
            } else {
                const int* __restrict__ Aind = (const int*)Aind_raw;
#pragma unroll
                for (int i = 0; i < TILE / 128; i += 4) {
                    int pa = p + (i + 0) * 128;
                    int pb = p + (i + 1) * 128;
                    int pc = p + (i + 2) * 128;
                    int pd = p + (i + 3) * 128;
                    int   ra = __ldcs(&Aind[pa]);
                    int   ca = __ldcs(&Aind[(size_t)nnz + pa]);
                    float va = __ldcs(&Aval[pa]);
                    int   rb = __ldcs(&Aind[pb]);
                    int   cb = __ldcs(&Aind[(size_t)nnz + pb]);
                    float vb = __ldcs(&Aval[pb]);
                    int   rc = __ldcs(&Aind[pc]);
                    int   cc = __ldcs(&Aind[(size_t)nnz + pc]);
                    float vc = __ldcs(&Aval[pc]);
                    int   rd = __ldcs(&Aind[pd]);
                    int   cd = __ldcs(&Aind[(size_t)nnz + pd]);
                    float vd = __ldcs(&Aval[pd]);
                    energy_step(ra, ca, va, h, N1, N2, N3, x4, acc);
                    energy_step(rb, cb, vb, h, N1, N2, N3, x4, acc);
                    energy_step(rc, cc, vc, h, N1, N2, N3, x4, acc);
                    energy_step(rd, cd, vd, h, N1, N2, N3, x4, acc);
                }
            }
        } else {
            // ---- TAIL: remainder tile (at most one block takes this) ----
            if (idx64) {
                const long long* __restrict__ Aind = (const long long*)Aind_raw;
                for (int p = ntiles_full * TILE + pair; p < nnz; p += 128) {
                    int   r = (int)__ldcs(&Aind[p]);
                    int   c = (int)__ldcs(&Aind[(size_t)nnz + p]);
                    float v = __ldcs(&Aval[p]);
                    energy_step(r, c, v, h, N1, N2, N3, x4, acc);
                }
            } else {
                const int* __restrict__ Aind = (const int*)Aind_raw;
                for (int p = ntiles_full * TILE + pair; p < nnz; p += 128) {
                    int   r = __ldcs(&Aind[p]);
                    int   c = __ldcs(&Aind[(size_t)nnz + p]);
                    float v = __ldcs(&Aval[p]);
                    energy_step(r, c, v, h, N1, N2, N3, x4, acc);
                }
            }
            // after the tail there is no more work
            break;
        }
    }

    // parity-preserving reduction -> lanes 0/1 -> shared -> 32 atomics
    {
        __shared__ float swarp[8 * ACC_TOTAL];
        int lane = threadIdx.x & 31;
        int wid  = threadIdx.x >> 5;
#pragma unroll
        for (int b = 0; b < NBATCH; b++)
#pragma unroll
            for (int s = 0; s < 4; s++) {
                float val = acc[b][s];
                val += __shfl_down_sync(0xFFFFFFFFu, val, 16);
                val += __shfl_down_sync(0xFFFFFFFFu, val, 8);
                val += __shfl_down_sync(0xFFFFFFFFu, val, 4);
                val += __shfl_down_sync(0xFFFFFFFFu, val, 2);
                if (lane < 2)   // lane0: s 0-3, lane1: s 4-7
                    swarp[wid * ACC_TOTAL + b * NSOL + h * 4 + s] = val;
            }
        __syncthreads();
        if (threadIdx.x < ACC_TOTAL) {
            float total = 0.0f;
#pragma unroll
            for (int w = 0; w < 8; w++) total += swarp[w * ACC_TOTAL + threadIdx.x];
            atomicAdd(&g_acc[threadIdx.x], total);
        }
    }

    try_finalize(out);
}

// ---------------------------------------------------------------------------
extern "C" void kernel_launch(void* const* d_in, const int* in_sizes, int n_in,
                              void* d_out, int out_size)
{
    // identify inputs by element count:
    // A_ind = 2*NNZ (max), A_val = NNZ, mass = B*N (min),
    // subspace = 4*B*N, x_hat = rhs = 8*B*N.
    long long maxs = -1, mins = 0x7fffffffffffffffLL;
    for (int i = 0; i < n_in; i++) {
        long long s = in_sizes[i];
        if (s > maxs) maxs = s;
        if (s < mins) mins = s;
    }
    int i_aind = -1, i_aval = -1, i_mass = -1, i_xr0 = -1, i_xr1 = -1;
    for (int i = 0; i < n_in; i++) {
        long long s = in_sizes[i];
        if (s == maxs)            i_aind = i;
        else if (2 * s == maxs)   i_aval = i;
        else if (s == mins)       i_mass = i;
        else if (s == 8 * mins) { if (i_xr0 < 0) i_xr0 = i; else i_xr1 = i; }
    }
    // dict order -> pair at (0,1) with x_hat first; alphabetical -> rhs first
    int i_x   = (i_xr0 == 0) ? i_xr0 : i_xr1;
    int i_rhs = (i_xr0 == 0) ? i_xr1 : i_xr0;

    const float* x_hat = (const float*)d_in[i_x];
    const float* rhs   = (const float*)d_in[i_rhs];
    const void*  A_ind = d_in[i_aind];
    const float* A_val = (const float*)d_in[i_aval];
    const float* mass  = (const float*)d_in[i_mass];

    int nnz = in_sizes[i_aval];
    int N   = in_sizes[i_mass] / NBATCH;

    fused_kernel<<<TOTAL_BLOCKS, 256>>>(A_ind, A_val, x_hat, rhs, mass,
                                        nnz, N, (float*)d_out);
}